// round 5
// baseline (speedup 1.0000x reference)
#include <cuda_runtime.h>
#include <cuda_bf16.h>

// GMMLoss: nll[b,m] = -logsumexp_n( c[b,n] - 0.5*dxy/sxy - 0.5*dz/sz ), output = mean(nll)
// Strategy: log2-domain, global per-batch LSE shift EST_b = max_n c2[b,n] (valid upper
// bound since distance terms <= 0), single pass, packed f32x2 math, n-split partials.

#define BDIM 4
#define NDIM 4096
#define MDIM 4096
#define TN   128            // n per block chunk
#define NCHUNK (NDIM / TN)  // 32
#define TM   512            // m per block (128 thr * 4)
#define NMT  (MDIM / TM)    // 8
#define BM   (BDIM * MDIM)  // 16384

#define EPSF     1e-8f
#define LOG2E    1.4426950408889634f
#define LN2      0.6931471805599453f
#define LOG_2PI  1.8378762f   /* log(2*3.14159) as in reference */

// Static scratch (no allocation allowed)
__device__ float g_params[BDIM * NDIM * 12];       // per n: {px,px, py,py, pz,pz, c2',c2', a2,a2, b2,b2}
__device__ float g_est[BDIM];
__device__ float g_partial[NCHUNK * BM];           // [chunk][b*M+m]
__device__ float g_bsum[64];

// ---------- packed f32x2 helpers ----------
__device__ __forceinline__ unsigned long long pk2(float lo, float hi) {
    unsigned long long r;
    asm("mov.b64 %0, {%1, %2};" : "=l"(r) : "f"(lo), "f"(hi));
    return r;
}
__device__ __forceinline__ void unpk2(unsigned long long v, float& lo, float& hi) {
    asm("mov.b64 {%0, %1}, %2;" : "=f"(lo), "=f"(hi) : "l"(v));
}
__device__ __forceinline__ unsigned long long add2(unsigned long long a, unsigned long long b) {
    unsigned long long r;
    asm("add.rn.f32x2 %0, %1, %2;" : "=l"(r) : "l"(a), "l"(b));
    return r;
}
__device__ __forceinline__ unsigned long long mul2(unsigned long long a, unsigned long long b) {
    unsigned long long r;
    asm("mul.rn.f32x2 %0, %1, %2;" : "=l"(r) : "l"(a), "l"(b));
    return r;
}
__device__ __forceinline__ unsigned long long fma2(unsigned long long a, unsigned long long b,
                                                   unsigned long long c) {
    unsigned long long r;
    asm("fma.rn.f32x2 %0, %1, %2, %3;" : "=l"(r) : "l"(a), "l"(b), "l"(c));
    return r;
}
__device__ __forceinline__ float ex2f(float x) {
    float r;
    asm("ex2.approx.ftz.f32 %0, %1;" : "=f"(r) : "f"(x));
    return r;
}

// ---------- kernel 1: per-batch EST = max_n c2 ----------
__global__ void kest(const float* __restrict__ sigma) {
    int b = blockIdx.x, tid = threadIdx.x;
    float mx = -1e30f;
    for (int n = tid; n < NDIM; n += 256) {
        float sxy = sigma[(b * NDIM + n) * 2 + 0] + EPSF;
        float sz  = sigma[(b * NDIM + n) * 2 + 1] + EPSF;
        float c2 = (-logf(sxy) - 0.5f * logf(sz) - 1.5f * LOG_2PI) * LOG2E;
        mx = fmaxf(mx, c2);
    }
    __shared__ float red[256];
    red[tid] = mx;
    __syncthreads();
    for (int s = 128; s > 0; s >>= 1) {
        if (tid < s) red[tid] = fmaxf(red[tid], red[tid + s]);
        __syncthreads();
    }
    if (tid == 0) g_est[b] = red[0];
}

// ---------- kernel 2: precompute duplicated packed params ----------
__global__ void kparams(const float* __restrict__ xyz, const float* __restrict__ sigma) {
    int idx = blockIdx.x * 256 + threadIdx.x;   // idx = b*N + n
    if (idx >= BDIM * NDIM) return;
    int b = idx >> 12;  // / NDIM
    float sxy = sigma[idx * 2 + 0] + EPSF;
    float sz  = sigma[idx * 2 + 1] + EPSF;
    float c2 = (-logf(sxy) - 0.5f * logf(sz) - 1.5f * LOG_2PI) * LOG2E - g_est[b];
    float a2 = -0.5f * LOG2E / sxy;
    float b2 = -0.5f * LOG2E / sz;
    float px = xyz[idx * 3 + 0], py = xyz[idx * 3 + 1], pz = xyz[idx * 3 + 2];
    float4* o = (float4*)(g_params + idx * 12);
    o[0] = make_float4(px, px, py, py);
    o[1] = make_float4(pz, pz, c2, c2);
    o[2] = make_float4(a2, a2, b2, b2);
}

// ---------- kernel 3: main pairwise sum-of-exp2 ----------
__global__ void __launch_bounds__(128) kmain(const float* __restrict__ tgt) {
    __shared__ float4 sm[TN * 3];  // 6 KB: duplicated per-n params for this chunk
    int chunk = blockIdx.x;        // 0..31
    int mt    = blockIdx.y;        // 0..7
    int b     = blockIdx.z;        // 0..3
    int tid   = threadIdx.x;

    // stage chunk params
    const float4* src = (const float4*)(g_params + (b * NDIM + chunk * TN) * 12);
    for (int i = tid; i < TN * 3; i += 128) sm[i] = src[i];

    // load 4 targets (negated, packed in pairs)
    int m0 = mt * TM + tid;
    const float* t = tgt + (size_t)(b * MDIM + m0) * 3;
    float tx[4], ty[4], tz[4];
#pragma unroll
    for (int k = 0; k < 4; k++) {
        tx[k] = -t[k * 128 * 3 + 0];
        ty[k] = -t[k * 128 * 3 + 1];
        tz[k] = -t[k * 128 * 3 + 2];
    }
    unsigned long long ntx0 = pk2(tx[0], tx[1]), nty0 = pk2(ty[0], ty[1]), ntz0 = pk2(tz[0], tz[1]);
    unsigned long long ntx1 = pk2(tx[2], tx[3]), nty1 = pk2(ty[2], ty[3]), ntz1 = pk2(tz[2], tz[3]);

    float s0 = 0.f, s1 = 0.f, s2 = 0.f, s3 = 0.f;
    __syncthreads();

#pragma unroll 4
    for (int ni = 0; ni < TN; ni++) {
        const ulonglong2* q = (const ulonglong2*)(sm + ni * 3);
        ulonglong2 A = q[0];   // {px,px},{py,py}
        ulonglong2 Bq = q[1];  // {pz,pz},{c2,c2}
        ulonglong2 Cq = q[2];  // {a2,a2},{b2,b2}

        // pair 0 (m0, m0+128)
        {
            unsigned long long dx = add2(A.x, ntx0);
            unsigned long long acc = mul2(dx, dx);
            unsigned long long dy = add2(A.y, nty0);
            acc = fma2(dy, dy, acc);
            unsigned long long dz = add2(Bq.x, ntz0);
            unsigned long long dzz = mul2(dz, dz);
            unsigned long long lp = fma2(Cq.x, acc, Bq.y);
            lp = fma2(Cq.y, dzz, lp);
            float lo, hi; unpk2(lp, lo, hi);
            s0 += ex2f(lo);
            s1 += ex2f(hi);
        }
        // pair 1 (m0+256, m0+384)
        {
            unsigned long long dx = add2(A.x, ntx1);
            unsigned long long acc = mul2(dx, dx);
            unsigned long long dy = add2(A.y, nty1);
            acc = fma2(dy, dy, acc);
            unsigned long long dz = add2(Bq.x, ntz1);
            unsigned long long dzz = mul2(dz, dz);
            unsigned long long lp = fma2(Cq.x, acc, Bq.y);
            lp = fma2(Cq.y, dzz, lp);
            float lo, hi; unpk2(lp, lo, hi);
            s2 += ex2f(lo);
            s3 += ex2f(hi);
        }
    }

    float* dst = g_partial + (size_t)chunk * BM + b * MDIM + m0;
    dst[0]       = s0;
    dst[128]     = s1;
    dst[256]     = s2;
    dst[384]     = s3;
}

// ---------- kernel 4: per-m LSE + block partial sums ----------
__global__ void klse() {
    int gm = blockIdx.x * 256 + threadIdx.x;  // 0..16383  (gm = b*M + m)
    float S = 0.f;
#pragma unroll
    for (int c = 0; c < NCHUNK; c++) S += g_partial[(size_t)c * BM + gm];
    int b = gm >> 12;  // / MDIM
    float nll = -LN2 * (g_est[b] + __log2f(fmaxf(S, 1e-37f)));
    __shared__ float red[256];
    red[threadIdx.x] = nll;
    __syncthreads();
    for (int s = 128; s > 0; s >>= 1) {
        if (threadIdx.x < s) red[threadIdx.x] += red[threadIdx.x + s];
        __syncthreads();
    }
    if (threadIdx.x == 0) g_bsum[blockIdx.x] = red[0];
}

// ---------- kernel 5: final mean ----------
__global__ void kfinal(float* out) {
    int tid = threadIdx.x;  // 64 threads
    __shared__ float red[64];
    red[tid] = g_bsum[tid];
    __syncthreads();
    for (int s = 32; s > 0; s >>= 1) {
        if (tid < s) red[tid] += red[tid + s];
        __syncthreads();
    }
    if (tid == 0) out[0] = red[0] * (1.0f / (float)BM);
}

extern "C" void kernel_launch(void* const* d_in, const int* in_sizes, int n_in,
                              void* d_out, int out_size) {
    const float* pred_xyz   = (const float*)d_in[0];  // (B,N,3)
    const float* pred_sigma = (const float*)d_in[1];  // (B,N,2)
    const float* target     = (const float*)d_in[2];  // (B,M,3)
    float* out = (float*)d_out;

    kest<<<BDIM, 256>>>(pred_sigma);
    kparams<<<(BDIM * NDIM + 255) / 256, 256>>>(pred_xyz, pred_sigma);
    kmain<<<dim3(NCHUNK, NMT, BDIM), 128>>>(target);
    klse<<<64, 256>>>();
    kfinal<<<1, 64>>>(out);
}

// round 6
// speedup vs baseline: 1.2734x; 1.2734x over previous
#include <cuda_runtime.h>
#include <cuda_bf16.h>

// GMMLoss: nll[b,m] = -logsumexp_n( c[b,n] - 0.5*dxy/sxy - 0.5*dz/sz ), out = mean(nll)
// log2-domain, FIXED LSE shift EST=40 (safe upper bound: c2 < 36, dist terms <= 0),
// expanded-quadratic 5-FMA inner loop, packed f32x2, n-split partials, 3 kernels.

#define BDIM 4
#define NDIM 4096
#define MDIM 4096
#define TN   128            // n per block chunk
#define NCHUNK (NDIM / TN)  // 32
#define TM   512            // m per block (128 thr * 4)
#define NMT  (MDIM / TM)    // 8
#define BM   (BDIM * MDIM)  // 16384

#define EPSF     1e-8f
#define LOG2E    1.4426950408889634f
#define LN2      0.6931471805599453f
#define LOG_2PI  1.8378762f      /* log(2*3.14159) per reference */
#define ESTC     40.0f           /* fixed log2-domain LSE shift */
#define NHALFL2E (-0.7213475f)   /* -0.5*log2e */

// Static scratch
__device__ float g_params[BDIM * NDIM * 12];  // per n: {K,K,a2,a2, b2,b2,u,u, v,v,w,w}
__device__ float g_partial[NCHUNK * BM];      // [chunk][b*M+m]
__device__ float g_bsum[64];
__device__ unsigned int g_flag;               // zero-init; self-resets each launch

// ---------- packed f32x2 helpers ----------
__device__ __forceinline__ unsigned long long pk2(float lo, float hi) {
    unsigned long long r;
    asm("mov.b64 %0, {%1, %2};" : "=l"(r) : "f"(lo), "f"(hi));
    return r;
}
__device__ __forceinline__ void unpk2(unsigned long long v, float& lo, float& hi) {
    asm("mov.b64 {%0, %1}, %2;" : "=f"(lo), "=f"(hi) : "l"(v));
}
__device__ __forceinline__ unsigned long long fma2(unsigned long long a, unsigned long long b,
                                                   unsigned long long c) {
    unsigned long long r;
    asm("fma.rn.f32x2 %0, %1, %2, %3;" : "=l"(r) : "l"(a), "l"(b), "l"(c));
    return r;
}
__device__ __forceinline__ float ex2f(float x) {
    float r;
    asm("ex2.approx.ftz.f32 %0, %1;" : "=f"(r) : "f"(x));
    return r;
}

// ---------- kernel 1: pure-map param precompute (EST is fixed) ----------
__global__ void __launch_bounds__(256) kprep(const float* __restrict__ xyz,
                                             const float* __restrict__ sigma) {
    int idx = blockIdx.x * 256 + threadIdx.x;  // 0..16383 = b*N+n
    float sxy = sigma[2 * idx + 0] + EPSF;
    float sz  = sigma[2 * idx + 1] + EPSF;
    // c2 in log2 units, pre-shifted by EST
    float c2 = -__log2f(sxy) - 0.5f * __log2f(sz) - 1.5f * LOG_2PI * LOG2E - ESTC;
    float a2 = __fdividef(NHALFL2E, sxy);
    float b2 = __fdividef(NHALFL2E, sz);
    float px = xyz[3 * idx + 0], py = xyz[3 * idx + 1], pz = xyz[3 * idx + 2];
    float K = fmaf(a2, fmaf(px, px, py * py), fmaf(b2, pz * pz, c2));
    float u = -2.0f * a2 * px;
    float v = -2.0f * a2 * py;
    float w = -2.0f * b2 * pz;
    float4* o = (float4*)(g_params + (size_t)idx * 12);
    o[0] = make_float4(K, K, a2, a2);
    o[1] = make_float4(b2, b2, u, u);
    o[2] = make_float4(v, v, w, w);
}

// ---------- kernel 2: main pairwise sum-of-exp2 ----------
__global__ void __launch_bounds__(128) kmain(const float* __restrict__ tgt) {
    __shared__ float4 sm[TN * 3];  // 6 KB duplicated per-n params
    int chunk = blockIdx.x;        // 0..31
    int mt    = blockIdx.y;        // 0..7
    int b     = blockIdx.z;        // 0..3
    int tid   = threadIdx.x;

    const float4* src = (const float4*)(g_params + (size_t)(b * NDIM + chunk * TN) * 12);
    for (int i = tid; i < TN * 3; i += 128) sm[i] = src[i];

    // 4 targets per thread, packed into 2 m-pairs
    int m0 = mt * TM + tid;
    const float* t = tgt + (size_t)(b * MDIM + m0) * 3;
    float tx[4], ty[4], tz[4], sxy[4], szl[4];
#pragma unroll
    for (int k = 0; k < 4; k++) {
        tx[k] = t[k * 128 * 3 + 0];
        ty[k] = t[k * 128 * 3 + 1];
        tz[k] = t[k * 128 * 3 + 2];
        sxy[k] = fmaf(tx[k], tx[k], ty[k] * ty[k]);
        szl[k] = tz[k] * tz[k];
    }
    unsigned long long TX0 = pk2(tx[0], tx[1]), TY0 = pk2(ty[0], ty[1]), TZ0 = pk2(tz[0], tz[1]);
    unsigned long long SXY0 = pk2(sxy[0], sxy[1]), SZ0 = pk2(szl[0], szl[1]);
    unsigned long long TX1 = pk2(tx[2], tx[3]), TY1 = pk2(ty[2], ty[3]), TZ1 = pk2(tz[2], tz[3]);
    unsigned long long SXY1 = pk2(sxy[2], sxy[3]), SZ1 = pk2(szl[2], szl[3]);

    float s0 = 0.f, s1 = 0.f, s2 = 0.f, s3 = 0.f;
    __syncthreads();

#pragma unroll 4
    for (int ni = 0; ni < TN; ni++) {
        const ulonglong2* q = (const ulonglong2*)(sm + ni * 3);
        ulonglong2 q0 = q[0];  // {K,K},{a2,a2}
        ulonglong2 q1 = q[1];  // {b2,b2},{u,u}
        ulonglong2 q2 = q[2];  // {v,v},{w,w}

        // pair 0 (m0, m0+128)
        {
            unsigned long long lp = fma2(q0.y, SXY0, q0.x);
            lp = fma2(q1.x, SZ0, lp);
            lp = fma2(q1.y, TX0, lp);
            lp = fma2(q2.x, TY0, lp);
            lp = fma2(q2.y, TZ0, lp);
            float lo, hi; unpk2(lp, lo, hi);
            s0 += ex2f(lo);
            s1 += ex2f(hi);
        }
        // pair 1 (m0+256, m0+384)
        {
            unsigned long long lp = fma2(q0.y, SXY1, q0.x);
            lp = fma2(q1.x, SZ1, lp);
            lp = fma2(q1.y, TX1, lp);
            lp = fma2(q2.x, TY1, lp);
            lp = fma2(q2.y, TZ1, lp);
            float lo, hi; unpk2(lp, lo, hi);
            s2 += ex2f(lo);
            s3 += ex2f(hi);
        }
    }

    float* dst = g_partial + (size_t)chunk * BM + b * MDIM + m0;
    dst[0]   = s0;
    dst[128] = s1;
    dst[256] = s2;
    dst[384] = s3;
}

// ---------- kernel 3: chunk-sum + LSE + full reduction (last-block pattern) ----------
__global__ void __launch_bounds__(256) kreduce(float* __restrict__ out) {
    int gm = blockIdx.x * 256 + threadIdx.x;  // 0..16383
    float S = 0.f;
#pragma unroll
    for (int c = 0; c < NCHUNK; c++) S += g_partial[(size_t)c * BM + gm];
    float nll = -LN2 * (ESTC + __log2f(fmaxf(S, 1e-37f)));

    __shared__ float red[256];
    red[threadIdx.x] = nll;
    __syncthreads();
    for (int s = 128; s > 0; s >>= 1) {
        if (threadIdx.x < s) red[threadIdx.x] += red[threadIdx.x + s];
        __syncthreads();
    }

    __shared__ bool islast;
    if (threadIdx.x == 0) {
        g_bsum[blockIdx.x] = red[0];
        __threadfence();
        unsigned int old = atomicAdd(&g_flag, 1u);
        islast = (old == 63u);
    }
    __syncthreads();

    if (islast) {
        // deterministic fixed-order final sum by thread 0's warp
        if (threadIdx.x == 0) {
            __threadfence();
            volatile float* bs = g_bsum;
            float acc = 0.f;
#pragma unroll
            for (int i = 0; i < 64; i++) acc += bs[i];
            out[0] = acc * (1.0f / (float)BM);
            g_flag = 0;  // reset for next graph replay
        }
    }
}

extern "C" void kernel_launch(void* const* d_in, const int* in_sizes, int n_in,
                              void* d_out, int out_size) {
    const float* pred_xyz   = (const float*)d_in[0];  // (B,N,3)
    const float* pred_sigma = (const float*)d_in[1];  // (B,N,2)
    const float* target     = (const float*)d_in[2];  // (B,M,3)
    float* out = (float*)d_out;

    kprep<<<(BDIM * NDIM) / 256, 256>>>(pred_xyz, pred_sigma);
    kmain<<<dim3(NCHUNK, NMT, BDIM), 128>>>(target);
    kreduce<<<64, 256>>>(out);
}